// round 4
// baseline (speedup 1.0000x reference)
#include <cuda_runtime.h>
#include <stdint.h>

// Problem constants
#define BDIM   1024
#define NSEQ   2304
#define NB     4
#define NH     16
#define HD     64
#define MROWS  (NB*NSEQ)      // 9216
#define HPATCH 48
#define GRP    8              // (b,h) pairs per attention group

// ---------------- scratch (static device globals; no allocation) -------------
__device__ float g_q [(size_t)NB*NH*NSEQ*HD];     // pre-rope  [b,h,n,d]
__device__ float g_k [(size_t)NB*NH*NSEQ*HD];
__device__ float g_v [(size_t)NB*NH*NSEQ*HD];
__device__ float g_q2[(size_t)NB*NH*NSEQ*HD];     // post-rope [b,h,n,d]
__device__ float g_k2[(size_t)NB*NH*NSEQ*HD];
__device__ float g_attn[(size_t)NB*NSEQ*BDIM];    // [b,n,D]
__device__ float g_S[(size_t)GRP*NSEQ*NSEQ];      // score scratch

// =============================================================================
// Deliberately simple projection GEMM: C[m][n] = sum_k X[m][k]*W[n][k] + b[n]
// 32x32 tile, 1024 threads, one output per thread, scalar smem loads.
// HEADSPLIT=1 writes [b, head, n, hd]; else flat [m][n].
// =============================================================================
template<int HEADSPLIT>
__global__ __launch_bounds__(1024)
void proj2_kernel(const float* __restrict__ X, const float* __restrict__ W,
                  const float* __restrict__ bias, float* __restrict__ out)
{
    __shared__ float Xs[32][33];
    __shared__ float Ws[32][33];

    const int tx = threadIdx.x;       // 0..31
    const int ty = threadIdx.y;       // 0..31
    const int m  = blockIdx.y * 32 + ty;
    const int n  = blockIdx.x * 32 + tx;

    float acc = 0.0f;
    for (int k0 = 0; k0 < BDIM; k0 += 32) {
        Xs[ty][tx] = X[(size_t)m * BDIM + k0 + tx];
        Ws[ty][tx] = W[(size_t)(blockIdx.x * 32 + ty) * BDIM + k0 + tx];
        __syncthreads();
        #pragma unroll
        for (int kk = 0; kk < 32; kk++)
            acc = fmaf(Xs[ty][kk], Ws[tx][kk], acc);
        __syncthreads();
    }
    acc += bias[n];

    if (HEADSPLIT) {
        int b    = m / NSEQ;
        int nn   = m - b * NSEQ;
        int head = n / HD;
        int hd0  = n - head * HD;
        out[(((size_t)(b*NH + head))*NSEQ + nn)*HD + hd0] = acc;
    } else {
        out[(size_t)m * BDIM + n] = acc;
    }
}

// =============================================================================
// Fresh 2D RoPE, out-of-place. One thread per rotation pair.
//   idx -> j (0..15), seg (0..1), t = (b*NH+h)*NSEQ + n
//   seg 0: dims (j, j+16),  angle = (n/48) * 10000^(-j/16)
//   seg 1: dims (32+j, 48+j), angle = (n%48) * 10000^(-j/16)
//   y1 = x1*cos - x2*sin ;  y2 = x1*sin + x2*cos
// =============================================================================
__global__ void rope2_kernel(const float* __restrict__ src,
                             float* __restrict__ dst)
{
    const int total = NB*NH*NSEQ*32;
    int idx = blockIdx.x * blockDim.x + threadIdx.x;
    if (idx >= total) return;

    int j   = idx % 16;
    int r   = idx / 16;
    int seg = r % 2;
    int t   = r / 2;                 // (b*NH+h)*NSEQ + n
    int n   = t % NSEQ;
    int hpos = n / HPATCH;
    int wpos = n - hpos * HPATCH;

    float pos  = (seg == 0) ? (float)hpos : (float)wpos;
    float freq = powf(10000.0f, -(float)j / 16.0f);
    float ang  = pos * freq;
    float c = cosf(ang);
    float s = sinf(ang);

    size_t b0 = (size_t)t * HD + seg * 32 + j;
    float x1 = src[b0];
    float x2 = src[b0 + 16];
    dst[b0]      = x1 * c - x2 * s;
    dst[b0 + 16] = x1 * s + x2 * c;
}

// =============================================================================
// Score GEMM: S[m][n] = 0.125 * q[m]·k[n], GRP (b,h) pairs per launch.
// (cross-validated stage; reads post-rope buffers)
// =============================================================================
__global__ __launch_bounds__(256)
void score_kernel(int bh0)
{
    __shared__ float As[16][132];
    __shared__ float Bs[16][132];

    const int tid = threadIdx.x;
    const int tx = tid & 15, ty = tid >> 4;
    const int bh = bh0 + blockIdx.z;
    const int m0 = blockIdx.y * 128;     // query tile
    const int n0 = blockIdx.x * 128;     // key tile

    const float* A = g_q2 + (size_t)bh * NSEQ * HD;
    const float* B = g_k2 + (size_t)bh * NSEQ * HD;
    float*       C = g_S  + (size_t)blockIdx.z * NSEQ * NSEQ;

    float acc[8][8];
    #pragma unroll
    for (int i = 0; i < 8; i++)
        #pragma unroll
        for (int j = 0; j < 8; j++) acc[i][j] = 0.f;

    for (int k0 = 0; k0 < HD; k0 += 16) {
        #pragma unroll
        for (int s = 0; s < 2; s++) {
            int lin = tid + s*256;
            int row = lin >> 2, kq = (lin & 3) * 4;
            float4 xa = *(const float4*)&A[(size_t)(m0+row)*HD + k0 + kq];
            As[kq+0][row] = xa.x; As[kq+1][row] = xa.y;
            As[kq+2][row] = xa.z; As[kq+3][row] = xa.w;
            float4 wb = *(const float4*)&B[(size_t)(n0+row)*HD + k0 + kq];
            Bs[kq+0][row] = wb.x; Bs[kq+1][row] = wb.y;
            Bs[kq+2][row] = wb.z; Bs[kq+3][row] = wb.w;
        }
        __syncthreads();

        #pragma unroll
        for (int kk = 0; kk < 16; kk++) {
            float a[8], b[8];
            *(float4*)&a[0] = *(float4*)&As[kk][ty*8];
            *(float4*)&a[4] = *(float4*)&As[kk][ty*8+4];
            *(float4*)&b[0] = *(float4*)&Bs[kk][tx*8];
            *(float4*)&b[4] = *(float4*)&Bs[kk][tx*8+4];
            #pragma unroll
            for (int i = 0; i < 8; i++)
                #pragma unroll
                for (int j = 0; j < 8; j++)
                    acc[i][j] = fmaf(a[i], b[j], acc[i][j]);
        }
        __syncthreads();
    }

    const float scale = 0.125f;   // 64^-0.5
    #pragma unroll
    for (int i = 0; i < 8; i++) {
        float* dst = &C[(size_t)(m0 + ty*8 + i)*NSEQ + n0 + tx*8];
        float4 c0 = make_float4(acc[i][0]*scale, acc[i][1]*scale,
                                acc[i][2]*scale, acc[i][3]*scale);
        float4 c1 = make_float4(acc[i][4]*scale, acc[i][5]*scale,
                                acc[i][6]*scale, acc[i][7]*scale);
        *(float4*)&dst[0] = c0;
        *(float4*)&dst[4] = c1;
    }
}

// =============================================================================
// Row softmax over g_S in place. One block per row; 2304 = 9*256.
// =============================================================================
__global__ __launch_bounds__(256)
void softmax_kernel()
{
    float* row = g_S + (size_t)blockIdx.y * NSEQ * NSEQ
                     + (size_t)blockIdx.x * NSEQ;
    __shared__ float red[256];
    const int tid = threadIdx.x;

    float v[9];
    float mx = -3.402823466e+38f;
    #pragma unroll
    for (int i = 0; i < 9; i++) {
        v[i] = row[tid + i*256];
        mx = fmaxf(mx, v[i]);
    }
    red[tid] = mx;
    __syncthreads();
    for (int s = 128; s > 0; s >>= 1) {
        if (tid < s) red[tid] = fmaxf(red[tid], red[tid+s]);
        __syncthreads();
    }
    mx = red[0];
    __syncthreads();

    float sum = 0.f;
    #pragma unroll
    for (int i = 0; i < 9; i++) {
        v[i] = expf(v[i] - mx);
        sum += v[i];
    }
    red[tid] = sum;
    __syncthreads();
    for (int s = 128; s > 0; s >>= 1) {
        if (tid < s) red[tid] += red[tid+s];
        __syncthreads();
    }
    float inv = 1.0f / red[0];

    #pragma unroll
    for (int i = 0; i < 9; i++)
        row[tid + i*256] = v[i] * inv;
}

// =============================================================================
// PV GEMM: O[m][d] = sum_c P[m][c] * V[c][d]. Writes g_attn [b, n, h*64 + d].
// =============================================================================
__global__ __launch_bounds__(256)
void pv_kernel(int bh0)
{
    __shared__ float Ps[32][132];   // [kk][row]  (transposed P tile)
    __shared__ float Vs[32][68];    // [kk][d]

    const int tid = threadIdx.x;
    const int tx = tid & 15, ty = tid >> 4;
    const int lb = blockIdx.z;
    const int bh = bh0 + lb;
    const int m0 = blockIdx.x * 128;

    const float* P = g_S + (size_t)lb * NSEQ * NSEQ;
    const float* V = g_v + (size_t)bh * NSEQ * HD;

    float acc[8][4];
    #pragma unroll
    for (int i = 0; i < 8; i++)
        #pragma unroll
        for (int j = 0; j < 4; j++) acc[i][j] = 0.f;

    for (int k0 = 0; k0 < NSEQ; k0 += 32) {
        #pragma unroll
        for (int s = 0; s < 4; s++) {
            int lin = tid + s*256;          // 128 rows x 8 float4
            int row = lin >> 3, kq = (lin & 7) * 4;
            float4 pv = *(const float4*)&P[(size_t)(m0+row)*NSEQ + k0 + kq];
            Ps[kq+0][row] = pv.x; Ps[kq+1][row] = pv.y;
            Ps[kq+2][row] = pv.z; Ps[kq+3][row] = pv.w;
        }
        #pragma unroll
        for (int s = 0; s < 2; s++) {
            int lin = tid + s*256;          // 32 rows x 16 float4
            int r = lin >> 4, d4 = (lin & 15) * 4;
            float4 vv = *(const float4*)&V[(size_t)(k0+r)*HD + d4];
            *(float4*)&Vs[r][d4] = vv;
        }
        __syncthreads();

        #pragma unroll
        for (int kk = 0; kk < 32; kk++) {
            float a[8], b[4];
            *(float4*)&a[0] = *(float4*)&Ps[kk][ty*8];
            *(float4*)&a[4] = *(float4*)&Ps[kk][ty*8+4];
            *(float4*)&b[0] = *(float4*)&Vs[kk][tx*4];
            #pragma unroll
            for (int i = 0; i < 8; i++)
                #pragma unroll
                for (int j = 0; j < 4; j++)
                    acc[i][j] = fmaf(a[i], b[j], acc[i][j]);
        }
        __syncthreads();
    }

    const int b = bh >> 4;
    const int h = bh & 15;
    #pragma unroll
    for (int i = 0; i < 8; i++) {
        int m = m0 + ty*8 + i;
        float4 o4 = make_float4(acc[i][0], acc[i][1], acc[i][2], acc[i][3]);
        *(float4*)&g_attn[((size_t)(b*NSEQ + m))*BDIM + h*HD + tx*4] = o4;
    }
}

// =============================================================================
// Launch. Binding: metadata dict order (confirmed by rounds 2 vs 3 agreement),
// with size-classification kept as a safety net.
// =============================================================================
extern "C" void kernel_launch(void* const* d_in, const int* in_sizes, int n_in,
                              void* d_out, int out_size)
{
    const float* big[3]  = {0,0,0};
    const float* Ws[4]   = {0,0,0,0};
    const float* bs[4]   = {0,0,0,0};
    int nbig = 0, nW = 0, nb = 0;
    for (int i = 0; i < n_in; i++) {
        int s = in_sizes[i];
        if (s == MROWS*BDIM)      { if (nbig < 3) big[nbig++] = (const float*)d_in[i]; }
        else if (s == BDIM*BDIM)  { if (nW  < 4) Ws[nW++]   = (const float*)d_in[i]; }
        else if (s == BDIM)       { if (nb  < 4) bs[nb++]   = (const float*)d_in[i]; }
    }
    const float* query = big[0];
    const float* key   = big[1];
    const float* value = big[2];
    const float* Wq = Ws[0]; const float* bq = bs[0];
    const float* Wk = Ws[1]; const float* bk = bs[1];
    const float* Wv = Ws[2]; const float* bv = bs[2];
    const float* Wo = Ws[3]; const float* bo = bs[3];

    float *qb, *kb, *vb, *q2b, *k2b, *ab;
    cudaGetSymbolAddress((void**)&qb,  g_q);
    cudaGetSymbolAddress((void**)&kb,  g_k);
    cudaGetSymbolAddress((void**)&vb,  g_v);
    cudaGetSymbolAddress((void**)&q2b, g_q2);
    cudaGetSymbolAddress((void**)&k2b, g_k2);
    cudaGetSymbolAddress((void**)&ab,  g_attn);

    dim3 pthr(32, 32);
    dim3 pg(BDIM/32, MROWS/32);     // (32, 288)
    proj2_kernel<1><<<pg, pthr>>>(query, Wq, bq, qb);
    proj2_kernel<1><<<pg, pthr>>>(key,   Wk, bk, kb);
    proj2_kernel<1><<<pg, pthr>>>(value, Wv, bv, vb);

    const int rtot = NB*NH*NSEQ*32;
    rope2_kernel<<<(rtot + 255)/256, 256>>>(qb, q2b);
    rope2_kernel<<<(rtot + 255)/256, 256>>>(kb, k2b);

    // attention: 8 groups of 8 (b,h) pairs, two-pass with materialized S
    for (int g = 0; g < NB*NH/GRP; g++) {
        score_kernel<<<dim3(NSEQ/128, NSEQ/128, GRP), 256>>>(g*GRP);
        softmax_kernel<<<dim3(NSEQ, GRP), 256>>>();
        pv_kernel<<<dim3(NSEQ/128, 1, GRP), 256>>>(g*GRP);
    }

    proj2_kernel<0><<<pg, pthr>>>(ab, Wo, bo, (float*)d_out);
}

// round 5
// speedup vs baseline: 4.0951x; 4.0951x over previous
#include <cuda_runtime.h>
#include <stdint.h>

// Problem constants
#define BDIM   1024
#define NSEQ   2304
#define NB     4
#define NH     16
#define HD     64
#define MROWS  (NB*NSEQ)      // 9216
#define HPATCH 48
#define GRP    16             // (b,h) pairs per attention group

// ---------------- scratch (static device globals; no allocation) -------------
__device__ float g_q [(size_t)NB*NH*NSEQ*HD];     // pre-rope  [b,h,n,d]
__device__ float g_k [(size_t)NB*NH*NSEQ*HD];
__device__ float g_v [(size_t)NB*NH*NSEQ*HD];
__device__ float g_q2[(size_t)NB*NH*NSEQ*HD];     // post-rope [b,h,n,d]
__device__ float g_k2[(size_t)NB*NH*NSEQ*HD];
__device__ float g_attn[(size_t)NB*NSEQ*BDIM];    // [b,n,D]
__device__ float g_S[(size_t)GRP*NSEQ*NSEQ];      // 340 MB score scratch

// ---------------- tf32 mma helpers -------------------------------------------
__device__ __forceinline__ uint32_t f2tf32(float x) {
    uint32_t r;
    asm("cvt.rna.tf32.f32 %0, %1;" : "=r"(r) : "f"(x));
    return r;
}

__device__ __forceinline__ void mma_tf32(float acc[4],
    uint32_t a0, uint32_t a1, uint32_t a2, uint32_t a3,
    uint32_t b0, uint32_t b1)
{
    asm volatile(
        "mma.sync.aligned.m16n8k8.row.col.f32.tf32.tf32.f32 "
        "{%0,%1,%2,%3}, {%4,%5,%6,%7}, {%8,%9}, {%0,%1,%2,%3};"
        : "+f"(acc[0]), "+f"(acc[1]), "+f"(acc[2]), "+f"(acc[3])
        : "r"(a0), "r"(a1), "r"(a2), "r"(a3), "r"(b0), "r"(b1));
}

// Block compute: As[128][36], Bs[128][36] (tf32 bits), BK=32.
// Warp tile 64(M) x 32(N): 4 m16-tiles x 4 n8-tiles. warpM in {0,1}, warpN in {0..3}.
__device__ __forceinline__ void block_mma_64x32(
    const uint32_t* __restrict__ As, const uint32_t* __restrict__ Bs,
    float acc[4][4][4], int lane, int warpM, int warpN)
{
    #pragma unroll
    for (int k8 = 0; k8 < 4; k8++) {
        const int kb = k8*8 + (lane & 3);
        uint32_t Af[4][4];
        #pragma unroll
        for (int mt = 0; mt < 4; mt++) {
            int r = warpM*64 + mt*16 + (lane >> 2);
            Af[mt][0] = As[r*36 + kb];
            Af[mt][1] = As[(r+8)*36 + kb];
            Af[mt][2] = As[r*36 + kb + 4];
            Af[mt][3] = As[(r+8)*36 + kb + 4];
        }
        uint32_t Bf[4][2];
        #pragma unroll
        for (int nt = 0; nt < 4; nt++) {
            int c = warpN*32 + nt*8 + (lane >> 2);
            Bf[nt][0] = Bs[c*36 + kb];
            Bf[nt][1] = Bs[c*36 + kb + 4];
        }
        #pragma unroll
        for (int mt = 0; mt < 4; mt++)
            #pragma unroll
            for (int nt = 0; nt < 4; nt++)
                mma_tf32(acc[mt][nt], Af[mt][0], Af[mt][1], Af[mt][2], Af[mt][3],
                         Bf[nt][0], Bf[nt][1]);
    }
}

// =============================================================================
// Projection GEMM (tf32 mma): C[m][n] = sum_k X[m][k]*W[n][k] + bias[n]
// Grid (BDIM/128, MROWS/128), 256 threads.
// =============================================================================
template<int HEADSPLIT>
__global__ __launch_bounds__(256, 2)
void proj_mma(const float* __restrict__ X, const float* __restrict__ W,
              const float* __restrict__ bias, float* __restrict__ out)
{
    __shared__ uint32_t As[128*36];
    __shared__ uint32_t Bs[128*36];

    const int tid   = threadIdx.x;
    const int lane  = tid & 31;
    const int wid   = tid >> 5;
    const int warpM = wid & 1;
    const int warpN = wid >> 1;
    const int m0 = blockIdx.y * 128;
    const int n0 = blockIdx.x * 128;

    float acc[4][4][4];
    #pragma unroll
    for (int a = 0; a < 4; a++)
        #pragma unroll
        for (int b = 0; b < 4; b++)
            #pragma unroll
            for (int c = 0; c < 4; c++) acc[a][b][c] = 0.f;

    for (int k0 = 0; k0 < BDIM; k0 += 32) {
        __syncthreads();
        #pragma unroll
        for (int s = 0; s < 4; s++) {
            int idx = tid + s*256;            // 0..1023 float4 ids
            int r   = idx >> 3;
            int kq  = (idx & 7) * 4;
            float4 xa = *(const float4*)&X[(size_t)(m0+r)*BDIM + k0 + kq];
            As[r*36 + kq + 0] = f2tf32(xa.x);
            As[r*36 + kq + 1] = f2tf32(xa.y);
            As[r*36 + kq + 2] = f2tf32(xa.z);
            As[r*36 + kq + 3] = f2tf32(xa.w);
            float4 wb = *(const float4*)&W[(size_t)(n0+r)*BDIM + k0 + kq];
            Bs[r*36 + kq + 0] = f2tf32(wb.x);
            Bs[r*36 + kq + 1] = f2tf32(wb.y);
            Bs[r*36 + kq + 2] = f2tf32(wb.z);
            Bs[r*36 + kq + 3] = f2tf32(wb.w);
        }
        __syncthreads();
        block_mma_64x32(As, Bs, acc, lane, warpM, warpN);
    }

    #pragma unroll
    for (int mt = 0; mt < 4; mt++) {
        int m = m0 + warpM*64 + mt*16 + (lane >> 2);
        #pragma unroll
        for (int nt = 0; nt < 4; nt++) {
            int n = n0 + warpN*32 + nt*8 + 2*(lane & 3);
            float b0v = __ldg(&bias[n]);
            float b1v = __ldg(&bias[n+1]);
            float v0 = acc[mt][nt][0] + b0v;
            float v1 = acc[mt][nt][1] + b1v;
            float v2 = acc[mt][nt][2] + b0v;
            float v3 = acc[mt][nt][3] + b1v;
            if (HEADSPLIT) {
                int b    = m / NSEQ;              // block never crosses batch
                int nn   = m - b*NSEQ;
                int head = n >> 6;
                int hd0  = n & 63;
                size_t base = (((size_t)(b*NH + head))*NSEQ + nn)*HD + hd0;
                *(float2*)&out[base]            = make_float2(v0, v1);
                *(float2*)&out[base + 8*HD]     = make_float2(v2, v3);  // m+8, same b/head
            } else {
                *(float2*)&out[(size_t)m*BDIM + n]       = make_float2(v0, v1);
                *(float2*)&out[(size_t)(m+8)*BDIM + n]   = make_float2(v2, v3);
            }
        }
    }
}

// =============================================================================
// 2D RoPE, out-of-place (verified in round 4, kept verbatim).
// =============================================================================
__global__ void rope2_kernel(const float* __restrict__ src,
                             float* __restrict__ dst)
{
    const int total = NB*NH*NSEQ*32;
    int idx = blockIdx.x * blockDim.x + threadIdx.x;
    if (idx >= total) return;

    int j   = idx % 16;
    int r   = idx / 16;
    int seg = r % 2;
    int t   = r / 2;                 // (b*NH+h)*NSEQ + n
    int n   = t % NSEQ;
    int hpos = n / HPATCH;
    int wpos = n - hpos * HPATCH;

    float pos  = (seg == 0) ? (float)hpos : (float)wpos;
    float freq = powf(10000.0f, -(float)j / 16.0f);
    float ang  = pos * freq;
    float c = cosf(ang);
    float s = sinf(ang);

    size_t b0 = (size_t)t * HD + seg * 32 + j;
    float x1 = src[b0];
    float x2 = src[b0 + 16];
    dst[b0]      = x1 * c - x2 * s;
    dst[b0 + 16] = x1 * s + x2 * c;
}

// =============================================================================
// Score GEMM (tf32 mma): S[m][n] = 0.125 * q2[m]·k2[n]. K=64 (2 BK iters).
// Grid (18, 18, GRP).
// =============================================================================
__global__ __launch_bounds__(256, 2)
void score_mma(int bh0)
{
    __shared__ uint32_t As[128*36];
    __shared__ uint32_t Bs[128*36];

    const int tid   = threadIdx.x;
    const int lane  = tid & 31;
    const int wid   = tid >> 5;
    const int warpM = wid & 1;
    const int warpN = wid >> 1;
    const int m0 = blockIdx.y * 128;
    const int n0 = blockIdx.x * 128;
    const int bh = bh0 + blockIdx.z;

    const float* A = g_q2 + (size_t)bh * NSEQ * HD;
    const float* B = g_k2 + (size_t)bh * NSEQ * HD;
    float*       C = g_S  + (size_t)blockIdx.z * NSEQ * NSEQ;

    float acc[4][4][4];
    #pragma unroll
    for (int a = 0; a < 4; a++)
        #pragma unroll
        for (int b = 0; b < 4; b++)
            #pragma unroll
            for (int c = 0; c < 4; c++) acc[a][b][c] = 0.f;

    for (int k0 = 0; k0 < HD; k0 += 32) {
        __syncthreads();
        #pragma unroll
        for (int s = 0; s < 4; s++) {
            int idx = tid + s*256;
            int r   = idx >> 3;
            int kq  = (idx & 7) * 4;
            float4 xa = *(const float4*)&A[(size_t)(m0+r)*HD + k0 + kq];
            As[r*36 + kq + 0] = f2tf32(xa.x);
            As[r*36 + kq + 1] = f2tf32(xa.y);
            As[r*36 + kq + 2] = f2tf32(xa.z);
            As[r*36 + kq + 3] = f2tf32(xa.w);
            float4 wb = *(const float4*)&B[(size_t)(n0+r)*HD + k0 + kq];
            Bs[r*36 + kq + 0] = f2tf32(wb.x);
            Bs[r*36 + kq + 1] = f2tf32(wb.y);
            Bs[r*36 + kq + 2] = f2tf32(wb.z);
            Bs[r*36 + kq + 3] = f2tf32(wb.w);
        }
        __syncthreads();
        block_mma_64x32(As, Bs, acc, lane, warpM, warpN);
    }

    const float sc = 0.125f;
    #pragma unroll
    for (int mt = 0; mt < 4; mt++) {
        int m = m0 + warpM*64 + mt*16 + (lane >> 2);
        #pragma unroll
        for (int nt = 0; nt < 4; nt++) {
            int n = n0 + warpN*32 + nt*8 + 2*(lane & 3);
            *(float2*)&C[(size_t)m*NSEQ + n] =
                make_float2(acc[mt][nt][0]*sc, acc[mt][nt][1]*sc);
            *(float2*)&C[(size_t)(m+8)*NSEQ + n] =
                make_float2(acc[mt][nt][2]*sc, acc[mt][nt][3]*sc);
        }
    }
}

// =============================================================================
// Row softmax over g_S in place (verified). One block per row; 2304 = 9*256.
// =============================================================================
__global__ __launch_bounds__(256)
void softmax_kernel()
{
    float* row = g_S + (size_t)blockIdx.y * NSEQ * NSEQ
                     + (size_t)blockIdx.x * NSEQ;
    __shared__ float red[256];
    const int tid = threadIdx.x;

    float v[9];
    float mx = -3.402823466e+38f;
    #pragma unroll
    for (int i = 0; i < 9; i++) {
        v[i] = row[tid + i*256];
        mx = fmaxf(mx, v[i]);
    }
    red[tid] = mx;
    __syncthreads();
    for (int s = 128; s > 0; s >>= 1) {
        if (tid < s) red[tid] = fmaxf(red[tid], red[tid+s]);
        __syncthreads();
    }
    mx = red[0];
    __syncthreads();

    float sum = 0.f;
    #pragma unroll
    for (int i = 0; i < 9; i++) {
        v[i] = expf(v[i] - mx);
        sum += v[i];
    }
    red[tid] = sum;
    __syncthreads();
    for (int s = 128; s > 0; s >>= 1) {
        if (tid < s) red[tid] += red[tid+s];
        __syncthreads();
    }
    float inv = 1.0f / red[0];

    #pragma unroll
    for (int i = 0; i < 9; i++)
        row[tid + i*256] = v[i] * inv;
}

// =============================================================================
// PV GEMM (tf32 mma), computed as O^T = V^T · P^T to keep natural layouts:
//   A = V^T (64 d x 2304 c): a-frag (row=d, k=c) read from Vs[c][d], stride 72
//   B = P^T (2304 c x 128 m): b-frag (k=c, col=m) read from Ps[m][c], stride 36
// Block: one bh, 128-m tile, all 64 d. 8 warps: warpD in {0,1} (32 d each,
// 2 m16-tiles), warpM in {0..3} (32 m each, 4 n8-tiles). BK=32 over c.
// Writes g_attn[b][m][h*64+d].
// =============================================================================
__global__ __launch_bounds__(256, 2)
void pv_mma(int bh0)
{
    __shared__ uint32_t Ps[128*36];   // P[m][c] tf32
    __shared__ uint32_t Vs[32*72];    // V[c][d] tf32

    const int tid   = threadIdx.x;
    const int lane  = tid & 31;
    const int wid   = tid >> 5;
    const int warpD = wid & 1;
    const int warpM = wid >> 1;
    const int m0 = blockIdx.x * 128;
    const int bh = bh0 + blockIdx.z;

    const float* P = g_S + (size_t)blockIdx.z * NSEQ * NSEQ;
    const float* V = g_v + (size_t)bh * NSEQ * HD;

    float acc[2][4][4];
    #pragma unroll
    for (int a = 0; a < 2; a++)
        #pragma unroll
        for (int b = 0; b < 4; b++)
            #pragma unroll
            for (int c = 0; c < 4; c++) acc[a][b][c] = 0.f;

    for (int kc = 0; kc < NSEQ; kc += 32) {
        __syncthreads();
        // P tile: 128 m-rows x 32 c
        #pragma unroll
        for (int s = 0; s < 4; s++) {
            int idx = tid + s*256;
            int r   = idx >> 3;
            int cq  = (idx & 7) * 4;
            float4 pv = *(const float4*)&P[(size_t)(m0+r)*NSEQ + kc + cq];
            Ps[r*36 + cq + 0] = f2tf32(pv.x);
            Ps[r*36 + cq + 1] = f2tf32(pv.y);
            Ps[r*36 + cq + 2] = f2tf32(pv.z);
            Ps[r*36 + cq + 3] = f2tf32(pv.w);
        }
        // V tile: 32 c-rows x 64 d
        #pragma unroll
        for (int s = 0; s < 2; s++) {
            int idx = tid + s*256;
            int c   = idx >> 4;
            int d4  = (idx & 15) * 4;
            float4 vv = *(const float4*)&V[(size_t)(kc+c)*HD + d4];
            Vs[c*72 + d4 + 0] = f2tf32(vv.x);
            Vs[c*72 + d4 + 1] = f2tf32(vv.y);
            Vs[c*72 + d4 + 2] = f2tf32(vv.z);
            Vs[c*72 + d4 + 3] = f2tf32(vv.w);
        }
        __syncthreads();

        #pragma unroll
        for (int k8 = 0; k8 < 4; k8++) {
            const int kb = k8*8 + (lane & 3);
            uint32_t Af[2][4];
            #pragma unroll
            for (int mt = 0; mt < 2; mt++) {
                int d = warpD*32 + mt*16 + (lane >> 2);
                Af[mt][0] = Vs[kb*72 + d];
                Af[mt][1] = Vs[kb*72 + d + 8];
                Af[mt][2] = Vs[(kb+4)*72 + d];
                Af[mt][3] = Vs[(kb+4)*72 + d + 8];
            }
            uint32_t Bf[4][2];
            #pragma unroll
            for (int nt = 0; nt < 4; nt++) {
                int mcol = warpM*32 + nt*8 + (lane >> 2);
                Bf[nt][0] = Ps[mcol*36 + kb];
                Bf[nt][1] = Ps[mcol*36 + kb + 4];
            }
            #pragma unroll
            for (int mt = 0; mt < 2; mt++)
                #pragma unroll
                for (int nt = 0; nt < 4; nt++)
                    mma_tf32(acc[mt][nt], Af[mt][0], Af[mt][1], Af[mt][2], Af[mt][3],
                             Bf[nt][0], Bf[nt][1]);
        }
    }

    const int b = bh >> 4;
    const int h = bh & 15;
    #pragma unroll
    for (int mt = 0; mt < 2; mt++) {
        int d = warpD*32 + mt*16 + (lane >> 2);
        #pragma unroll
        for (int nt = 0; nt < 4; nt++) {
            int m = m0 + warpM*32 + nt*8 + 2*(lane & 3);
            size_t r0 = ((size_t)(b*NSEQ + m))*BDIM + h*HD;
            g_attn[r0 + d]              = acc[mt][nt][0];
            g_attn[r0 + BDIM + d]       = acc[mt][nt][1];   // m+1
            g_attn[r0 + d + 8]          = acc[mt][nt][2];   // d+8
            g_attn[r0 + BDIM + d + 8]   = acc[mt][nt][3];
        }
    }
}

// =============================================================================
// Launch. Binding: size-classified (order-robust, verified in round 4).
// =============================================================================
extern "C" void kernel_launch(void* const* d_in, const int* in_sizes, int n_in,
                              void* d_out, int out_size)
{
    const float* big[3]  = {0,0,0};
    const float* Ws[4]   = {0,0,0,0};
    const float* bs[4]   = {0,0,0,0};
    int nbig = 0, nW = 0, nb = 0;
    for (int i = 0; i < n_in; i++) {
        int s = in_sizes[i];
        if (s == MROWS*BDIM)      { if (nbig < 3) big[nbig++] = (const float*)d_in[i]; }
        else if (s == BDIM*BDIM)  { if (nW  < 4) Ws[nW++]   = (const float*)d_in[i]; }
        else if (s == BDIM)       { if (nb  < 4) bs[nb++]   = (const float*)d_in[i]; }
    }
    const float* query = big[0];
    const float* key   = big[1];
    const float* value = big[2];
    const float* Wq = Ws[0]; const float* bq = bs[0];
    const float* Wk = Ws[1]; const float* bk = bs[1];
    const float* Wv = Ws[2]; const float* bv = bs[2];
    const float* Wo = Ws[3]; const float* bo = bs[3];

    float *qb, *kb, *vb, *q2b, *k2b, *ab;
    cudaGetSymbolAddress((void**)&qb,  g_q);
    cudaGetSymbolAddress((void**)&kb,  g_k);
    cudaGetSymbolAddress((void**)&vb,  g_v);
    cudaGetSymbolAddress((void**)&q2b, g_q2);
    cudaGetSymbolAddress((void**)&k2b, g_k2);
    cudaGetSymbolAddress((void**)&ab,  g_attn);

    dim3 pg(BDIM/128, MROWS/128);   // (8, 72)
    proj_mma<1><<<pg, 256>>>(query, Wq, bq, qb);
    proj_mma<1><<<pg, 256>>>(key,   Wk, bk, kb);
    proj_mma<1><<<pg, 256>>>(value, Wv, bv, vb);

    const int rtot = NB*NH*NSEQ*32;
    rope2_kernel<<<(rtot + 255)/256, 256>>>(qb, q2b);
    rope2_kernel<<<(rtot + 255)/256, 256>>>(kb, k2b);

    // attention: 4 groups of 16 (b,h) pairs, two-pass with materialized S
    for (int g = 0; g < NB*NH/GRP; g++) {
        score_mma<<<dim3(NSEQ/128, NSEQ/128, GRP), 256>>>(g*GRP);
        softmax_kernel<<<dim3(NSEQ, GRP), 256>>>();
        pv_mma<<<dim3(NSEQ/128, 1, GRP), 256>>>(g*GRP);
    }

    proj_mma<0><<<pg, 256>>>(ab, Wo, bo, (float*)d_out);
}

// round 7
// speedup vs baseline: 6.1176x; 1.4939x over previous
#include <cuda_runtime.h>
#include <cuda_bf16.h>
#include <stdint.h>
#include <string.h>

// Problem constants
#define BDIM   1024
#define NSEQ   2304
#define NB     4
#define NH     16
#define HD     64
#define MROWS  (NB*NSEQ)      // 9216
#define HPATCH 48

// ---------------- scratch (static device globals; no allocation) -------------
__device__ float g_q [(size_t)NB*NH*NSEQ*HD];     // pre-rope  [b,h,n,d]
__device__ float g_k [(size_t)NB*NH*NSEQ*HD];
__device__ float g_v [(size_t)NB*NH*NSEQ*HD];
__device__ float g_q2[(size_t)NB*NH*NSEQ*HD];     // post-rope [b,h,n,d]
__device__ float g_k2[(size_t)NB*NH*NSEQ*HD];
__device__ float g_attn[(size_t)NB*NSEQ*BDIM];    // [b,n,D]

// ---------------- bf16 helpers -----------------------------------------------
__device__ __forceinline__ uint32_t pack2(float a, float b) {
    __nv_bfloat16 ha = __float2bfloat16_rn(a);
    __nv_bfloat16 hb = __float2bfloat16_rn(b);
    uint16_t ra, rb;
    memcpy(&ra, &ha, 2); memcpy(&rb, &hb, 2);
    return (uint32_t)ra | ((uint32_t)rb << 16);
}
__device__ __forceinline__ float lo_of(float x) {
    return x - __bfloat162float(__float2bfloat16_rn(x));
}
__device__ __forceinline__ float ex2_approx(float x) {
    float r;
    asm("ex2.approx.ftz.f32 %0, %1;" : "=f"(r) : "f"(x));
    return r;
}

__device__ __forceinline__ void mma_bf16(float acc[4],
    uint32_t a0, uint32_t a1, uint32_t a2, uint32_t a3,
    uint32_t b0, uint32_t b1)
{
    asm volatile(
        "mma.sync.aligned.m16n8k16.row.col.f32.bf16.bf16.f32 "
        "{%0,%1,%2,%3}, {%4,%5,%6,%7}, {%8,%9}, {%0,%1,%2,%3};"
        : "+f"(acc[0]), "+f"(acc[1]), "+f"(acc[2]), "+f"(acc[3])
        : "r"(a0), "r"(a1), "r"(a2), "r"(a3), "r"(b0), "r"(b1));
}

// =============================================================================
// Projection GEMM (bf16x3): C[m][n] = sum_k X[m][k]*W[n][k] + bias[n]
// 128x128 block, 256 threads, BK=32, warp tile 64x32.
// Smem rows: 32 bf16 payload in 40-bf16 (20-word) stride -> conflict-free.
// =============================================================================
template<int HEADSPLIT>
__global__ __launch_bounds__(256, 2)
void proj_mma3(const float* __restrict__ X, const float* __restrict__ W,
               const float* __restrict__ bias, float* __restrict__ out)
{
    __shared__ __nv_bfloat16 Xh[128*40], Xl[128*40];
    __shared__ __nv_bfloat16 Wh[128*40], Wl[128*40];
    uint32_t* Xh32 = (uint32_t*)Xh;  uint32_t* Xl32 = (uint32_t*)Xl;
    uint32_t* Wh32 = (uint32_t*)Wh;  uint32_t* Wl32 = (uint32_t*)Wl;

    const int tid   = threadIdx.x;
    const int lane  = tid & 31;
    const int wid   = tid >> 5;
    const int warpM = wid & 1;
    const int warpN = wid >> 1;
    const int c     = lane & 3;
    const int lr    = lane >> 2;
    const int m0 = blockIdx.y * 128;
    const int n0 = blockIdx.x * 128;

    float acc[4][4][4];
    #pragma unroll
    for (int a = 0; a < 4; a++)
        #pragma unroll
        for (int b = 0; b < 4; b++)
            #pragma unroll
            for (int d = 0; d < 4; d++) acc[a][b][d] = 0.f;

    for (int k0 = 0; k0 < BDIM; k0 += 32) {
        __syncthreads();
        #pragma unroll
        for (int s = 0; s < 4; s++) {
            int idx = tid + s*256;            // 0..1023 float4 ids (128 x 8)
            int r   = idx >> 3;
            int kq  = (idx & 7) * 4;
            int w0  = r*20 + (kq >> 1);
            float4 xa = *(const float4*)&X[(size_t)(m0+r)*BDIM + k0 + kq];
            Xh32[w0    ] = pack2(xa.x, xa.y);
            Xh32[w0 + 1] = pack2(xa.z, xa.w);
            Xl32[w0    ] = pack2(lo_of(xa.x), lo_of(xa.y));
            Xl32[w0 + 1] = pack2(lo_of(xa.z), lo_of(xa.w));
            float4 wb = *(const float4*)&W[(size_t)(n0+r)*BDIM + k0 + kq];
            Wh32[w0    ] = pack2(wb.x, wb.y);
            Wh32[w0 + 1] = pack2(wb.z, wb.w);
            Wl32[w0    ] = pack2(lo_of(wb.x), lo_of(wb.y));
            Wl32[w0 + 1] = pack2(lo_of(wb.z), lo_of(wb.w));
        }
        __syncthreads();

        #pragma unroll
        for (int kt = 0; kt < 2; kt++) {
            uint32_t ah[4][4], al[4][4];
            #pragma unroll
            for (int mt = 0; mt < 4; mt++) {
                int rA = warpM*64 + mt*16 + lr;
                int w  = rA*20 + kt*8 + c;
                ah[mt][0] = Xh32[w];        ah[mt][1] = Xh32[w + 8*20];
                ah[mt][2] = Xh32[w + 4];    ah[mt][3] = Xh32[w + 8*20 + 4];
                al[mt][0] = Xl32[w];        al[mt][1] = Xl32[w + 8*20];
                al[mt][2] = Xl32[w + 4];    al[mt][3] = Xl32[w + 8*20 + 4];
            }
            uint32_t bh[4][2], bl[4][2];
            #pragma unroll
            for (int nt = 0; nt < 4; nt++) {
                int nB = warpN*32 + nt*8 + lr;
                int w  = nB*20 + kt*8 + c;
                bh[nt][0] = Wh32[w];  bh[nt][1] = Wh32[w + 4];
                bl[nt][0] = Wl32[w];  bl[nt][1] = Wl32[w + 4];
            }
            #pragma unroll
            for (int mt = 0; mt < 4; mt++)
                #pragma unroll
                for (int nt = 0; nt < 4; nt++) {
                    mma_bf16(acc[mt][nt], ah[mt][0], ah[mt][1], ah[mt][2], ah[mt][3],
                             bh[nt][0], bh[nt][1]);
                    mma_bf16(acc[mt][nt], ah[mt][0], ah[mt][1], ah[mt][2], ah[mt][3],
                             bl[nt][0], bl[nt][1]);
                    mma_bf16(acc[mt][nt], al[mt][0], al[mt][1], al[mt][2], al[mt][3],
                             bh[nt][0], bh[nt][1]);
                }
        }
    }

    #pragma unroll
    for (int mt = 0; mt < 4; mt++) {
        int m = m0 + warpM*64 + mt*16 + lr;
        #pragma unroll
        for (int nt = 0; nt < 4; nt++) {
            int n = n0 + warpN*32 + nt*8 + 2*c;
            float b0v = __ldg(&bias[n]);
            float b1v = __ldg(&bias[n+1]);
            float v0 = acc[mt][nt][0] + b0v;
            float v1 = acc[mt][nt][1] + b1v;
            float v2 = acc[mt][nt][2] + b0v;
            float v3 = acc[mt][nt][3] + b1v;
            if (HEADSPLIT) {
                int b    = m / NSEQ;              // tile never crosses batch
                int nn   = m - b*NSEQ;
                int head = n >> 6;
                int hd0  = n & 63;
                size_t base = (((size_t)(b*NH + head))*NSEQ + nn)*HD + hd0;
                *(float2*)&out[base]        = make_float2(v0, v1);
                *(float2*)&out[base + 8*HD] = make_float2(v2, v3);  // m+8
            } else {
                *(float2*)&out[(size_t)m*BDIM + n]     = make_float2(v0, v1);
                *(float2*)&out[(size_t)(m+8)*BDIM + n] = make_float2(v2, v3);
            }
        }
    }
}

// =============================================================================
// 2D RoPE, out-of-place (verified round 4, kept verbatim).
// =============================================================================
__global__ void rope2_kernel(const float* __restrict__ src,
                             float* __restrict__ dst)
{
    const int total = NB*NH*NSEQ*32;
    int idx = blockIdx.x * blockDim.x + threadIdx.x;
    if (idx >= total) return;

    int j   = idx % 16;
    int r   = idx / 16;
    int seg = r % 2;
    int t   = r / 2;                 // (b*NH+h)*NSEQ + n
    int n   = t % NSEQ;
    int hpos = n / HPATCH;
    int wpos = n - hpos * HPATCH;

    float pos  = (seg == 0) ? (float)hpos : (float)wpos;
    float freq = powf(10000.0f, -(float)j / 16.0f);
    float ang  = pos * freq;
    float cc = cosf(ang);
    float ss = sinf(ang);

    size_t b0 = (size_t)t * HD + seg * 32 + j;
    float x1 = src[b0];
    float x2 = src[b0 + 16];
    dst[b0]      = x1 * cc - x2 * ss;
    dst[b0 + 16] = x1 * ss + x2 * cc;
}

// =============================================================================
// Flash attention (bf16x3 mma, log2-domain online softmax).
// Block: 128 q-rows x one bh. 8 warps, each owns 16 q-rows, full n/d width.
// KV tiles of 64. Q fragments register-resident (staged once via smem).
// P stays in registers: S-accum fragment layout == PV A-fragment layout.
// ALL smem rows use 36-WORD (72 bf16) stride: fits the 32-word (64 bf16)
// payload, and banks (4r+c) are distinct across a quad (36 mod 32 == 4).
// =============================================================================
#define FW 36            // row stride in words for K / V^T / staged Q
#define QSC  0.18033688011112042f   // 0.125 * log2(e)

__global__ __launch_bounds__(256)
void flash_kernel()
{
    __shared__ __nv_bfloat16 smem[4 * 64 * 72];    // 36864 B
    __nv_bfloat16* Ksh = smem;                     // 64 rows * 72
    __nv_bfloat16* Ksl = Ksh + 64*72;
    __nv_bfloat16* Vsh = Ksl + 64*72;              // 64 d-rows * 72
    __nv_bfloat16* Vsl = Vsh + 64*72;
    uint32_t* Ksh32 = (uint32_t*)Ksh;  uint32_t* Ksl32 = (uint32_t*)Ksl;
    uint32_t* Vsh32 = (uint32_t*)Vsh;  uint32_t* Vsl32 = (uint32_t*)Vsl;

    const int tid  = threadIdx.x;
    const int lane = tid & 31;
    const int wid  = tid >> 5;
    const int c    = lane & 3;
    const int lr   = lane >> 2;
    const int q0   = blockIdx.x * 128;
    const int bh   = blockIdx.y;

    const float* qp = g_q2 + (size_t)bh * NSEQ * HD;
    const float* kp = g_k2 + (size_t)bh * NSEQ * HD;
    const float* vp = g_v  + (size_t)bh * NSEQ * HD;

    // ---- stage Q (hi in first half of smem, lo in second half), stride FW
    uint32_t* Qh32 = (uint32_t*)smem;              // 128*36 words = 18432 B
    uint32_t* Ql32 = Qh32 + 128*FW;                // next 18432 B
    #pragma unroll
    for (int s = 0; s < 8; s++) {
        int idx = tid + s*256;                 // 0..2047 float4 ids (128 x 16)
        int r   = idx >> 4;
        int dq  = (idx & 15) * 4;
        float4 qv = *(const float4*)&qp[(size_t)(q0+r)*HD + dq];
        int w0 = r*FW + (dq >> 1);
        Qh32[w0    ] = pack2(qv.x, qv.y);
        Qh32[w0 + 1] = pack2(qv.z, qv.w);
        Ql32[w0    ] = pack2(lo_of(qv.x), lo_of(qv.y));
        Ql32[w0 + 1] = pack2(lo_of(qv.z), lo_of(qv.w));
    }
    __syncthreads();

    // ---- load Q fragments (warp wid owns rows wid*16 .. +15)
    uint32_t qh[4][4], ql[4][4];
    {
        int rA = wid*16 + lr;
        #pragma unroll
        for (int kt = 0; kt < 4; kt++) {
            int w = rA*FW + kt*8 + c;
            qh[kt][0] = Qh32[w];      qh[kt][1] = Qh32[w + 8*FW];
            qh[kt][2] = Qh32[w + 4];  qh[kt][3] = Qh32[w + 8*FW + 4];
            ql[kt][0] = Ql32[w];      ql[kt][1] = Ql32[w + 8*FW];
            ql[kt][2] = Ql32[w + 4];  ql[kt][3] = Ql32[w + 8*FW + 4];
        }
    }
    __syncthreads();

    float m0r = -__int_as_float(0x7f800000), m1r = m0r;   // -inf (log2 units)
    float l0 = 0.f, l1 = 0.f;
    float O[8][4];
    #pragma unroll
    for (int dt = 0; dt < 8; dt++)
        #pragma unroll
        for (int j = 0; j < 4; j++) O[dt][j] = 0.f;

    for (int kv0 = 0; kv0 < NSEQ; kv0 += 64) {
        // ---- load K (row-major) and V (transposed), hi+lo splits
        #pragma unroll
        for (int s = 0; s < 4; s++) {
            int idx = tid + s*256;             // 0..1023 float4 ids (64 x 16)
            int kv  = idx >> 4;
            int dq  = (idx & 15) * 4;
            float4 kvv = *(const float4*)&kp[(size_t)(kv0+kv)*HD + dq];
            int w0 = kv*FW + (dq >> 1);
            Ksh32[w0    ] = pack2(kvv.x, kvv.y);
            Ksh32[w0 + 1] = pack2(kvv.z, kvv.w);
            Ksl32[w0    ] = pack2(lo_of(kvv.x), lo_of(kvv.y));
            Ksl32[w0 + 1] = pack2(lo_of(kvv.z), lo_of(kvv.w));
            float4 vv = *(const float4*)&vp[(size_t)(kv0+kv)*HD + dq];
            float vf[4] = {vv.x, vv.y, vv.z, vv.w};
            #pragma unroll
            for (int j = 0; j < 4; j++) {
                Vsh[(dq+j)*72 + kv] = __float2bfloat16_rn(vf[j]);
                Vsl[(dq+j)*72 + kv] = __float2bfloat16_rn(lo_of(vf[j]));
            }
        }
        __syncthreads();

        // ---- S = Q K^T (bf16x3), fp32 accum
        float sacc[8][4];
        #pragma unroll
        for (int nt = 0; nt < 8; nt++)
            #pragma unroll
            for (int j = 0; j < 4; j++) sacc[nt][j] = 0.f;

        #pragma unroll
        for (int kt = 0; kt < 4; kt++) {
            #pragma unroll
            for (int nt = 0; nt < 8; nt++) {
                int nB = nt*8 + lr;
                int w  = nB*FW + kt*8 + c;
                uint32_t kb0 = Ksh32[w], kb1 = Ksh32[w + 4];
                uint32_t lb0 = Ksl32[w], lb1 = Ksl32[w + 4];
                mma_bf16(sacc[nt], qh[kt][0], qh[kt][1], qh[kt][2], qh[kt][3], kb0, kb1);
                mma_bf16(sacc[nt], qh[kt][0], qh[kt][1], qh[kt][2], qh[kt][3], lb0, lb1);
                mma_bf16(sacc[nt], ql[kt][0], ql[kt][1], ql[kt][2], ql[kt][3], kb0, kb1);
            }
        }

        // ---- scale to log2 units
        #pragma unroll
        for (int nt = 0; nt < 8; nt++)
            #pragma unroll
            for (int j = 0; j < 4; j++) sacc[nt][j] *= QSC;

        // ---- online softmax (rows r=lr and r+8; quad = lanes sharing lr)
        float mx0 = -__int_as_float(0x7f800000), mx1 = mx0;
        #pragma unroll
        for (int nt = 0; nt < 8; nt++) {
            mx0 = fmaxf(mx0, fmaxf(sacc[nt][0], sacc[nt][1]));
            mx1 = fmaxf(mx1, fmaxf(sacc[nt][2], sacc[nt][3]));
        }
        mx0 = fmaxf(mx0, __shfl_xor_sync(0xffffffffu, mx0, 1));
        mx0 = fmaxf(mx0, __shfl_xor_sync(0xffffffffu, mx0, 2));
        mx1 = fmaxf(mx1, __shfl_xor_sync(0xffffffffu, mx1, 1));
        mx1 = fmaxf(mx1, __shfl_xor_sync(0xffffffffu, mx1, 2));

        float mn0 = fmaxf(m0r, mx0);
        float mn1 = fmaxf(m1r, mx1);
        float cr0 = ex2_approx(m0r - mn0);
        float cr1 = ex2_approx(m1r - mn1);
        m0r = mn0; m1r = mn1;

        float rs0 = 0.f, rs1 = 0.f;
        #pragma unroll
        for (int nt = 0; nt < 8; nt++) {
            sacc[nt][0] = ex2_approx(sacc[nt][0] - mn0);
            sacc[nt][1] = ex2_approx(sacc[nt][1] - mn0);
            sacc[nt][2] = ex2_approx(sacc[nt][2] - mn1);
            sacc[nt][3] = ex2_approx(sacc[nt][3] - mn1);
            rs0 += sacc[nt][0] + sacc[nt][1];
            rs1 += sacc[nt][2] + sacc[nt][3];
        }
        rs0 += __shfl_xor_sync(0xffffffffu, rs0, 1);
        rs0 += __shfl_xor_sync(0xffffffffu, rs0, 2);
        rs1 += __shfl_xor_sync(0xffffffffu, rs1, 1);
        rs1 += __shfl_xor_sync(0xffffffffu, rs1, 2);
        l0 = l0 * cr0 + rs0;
        l1 = l1 * cr1 + rs1;

        #pragma unroll
        for (int dt = 0; dt < 8; dt++) {
            O[dt][0] *= cr0; O[dt][1] *= cr0;
            O[dt][2] *= cr1; O[dt][3] *= cr1;
        }

        // ---- O += P V (bf16x3); P from registers (S nt=2kt,2kt+1 -> A-frag kt)
        #pragma unroll
        for (int kt = 0; kt < 4; kt++) {
            uint32_t pa[4], pl[4];
            pa[0] = pack2(sacc[2*kt][0],   sacc[2*kt][1]);
            pa[1] = pack2(sacc[2*kt][2],   sacc[2*kt][3]);
            pa[2] = pack2(sacc[2*kt+1][0], sacc[2*kt+1][1]);
            pa[3] = pack2(sacc[2*kt+1][2], sacc[2*kt+1][3]);
            pl[0] = pack2(lo_of(sacc[2*kt][0]),   lo_of(sacc[2*kt][1]));
            pl[1] = pack2(lo_of(sacc[2*kt][2]),   lo_of(sacc[2*kt][3]));
            pl[2] = pack2(lo_of(sacc[2*kt+1][0]), lo_of(sacc[2*kt+1][1]));
            pl[3] = pack2(lo_of(sacc[2*kt+1][2]), lo_of(sacc[2*kt+1][3]));
            #pragma unroll
            for (int dt = 0; dt < 8; dt++) {
                int w = (dt*8 + lr)*FW + kt*8 + c;
                uint32_t vb0 = Vsh32[w], vb1 = Vsh32[w + 4];
                uint32_t wl0 = Vsl32[w], wl1 = Vsl32[w + 4];
                mma_bf16(O[dt], pa[0], pa[1], pa[2], pa[3], vb0, vb1);
                mma_bf16(O[dt], pa[0], pa[1], pa[2], pa[3], wl0, wl1);
                mma_bf16(O[dt], pl[0], pl[1], pl[2], pl[3], vb0, vb1);
            }
        }
        __syncthreads();
    }

    // ---- finalize: /= l, write to g_attn [b, n, h*64 + d]
    const int b = bh >> 4;
    const int h = bh & 15;
    float inv0 = 1.0f / l0;
    float inv1 = 1.0f / l1;
    int row0 = q0 + wid*16 + lr;
    #pragma unroll
    for (int dt = 0; dt < 8; dt++) {
        int d = dt*8 + 2*c;
        size_t r0 = ((size_t)(b*NSEQ + row0))*BDIM + h*HD + d;
        *(float2*)&g_attn[r0]           = make_float2(O[dt][0]*inv0, O[dt][1]*inv0);
        *(float2*)&g_attn[r0 + 8*BDIM]  = make_float2(O[dt][2]*inv1, O[dt][3]*inv1);
    }
}

// =============================================================================
// Launch. Binding: size-classified (order-robust, verified in round 4).
// =============================================================================
extern "C" void kernel_launch(void* const* d_in, const int* in_sizes, int n_in,
                              void* d_out, int out_size)
{
    const float* big[3]  = {0,0,0};
    const float* Ws[4]   = {0,0,0,0};
    const float* bs[4]   = {0,0,0,0};
    int nbig = 0, nW = 0, nb = 0;
    for (int i = 0; i < n_in; i++) {
        int s = in_sizes[i];
        if (s == MROWS*BDIM)      { if (nbig < 3) big[nbig++] = (const float*)d_in[i]; }
        else if (s == BDIM*BDIM)  { if (nW  < 4) Ws[nW++]   = (const float*)d_in[i]; }
        else if (s == BDIM)       { if (nb  < 4) bs[nb++]   = (const float*)d_in[i]; }
    }
    const float* query = big[0];
    const float* key   = big[1];
    const float* value = big[2];
    const float* Wq = Ws[0]; const float* bq = bs[0];
    const float* Wk = Ws[1]; const float* bk = bs[1];
    const float* Wv = Ws[2]; const float* bv = bs[2];
    const float* Wo = Ws[3]; const float* bo = bs[3];

    float *qb, *kb, *vb, *q2b, *k2b, *ab;
    cudaGetSymbolAddress((void**)&qb,  g_q);
    cudaGetSymbolAddress((void**)&kb,  g_k);
    cudaGetSymbolAddress((void**)&vb,  g_v);
    cudaGetSymbolAddress((void**)&q2b, g_q2);
    cudaGetSymbolAddress((void**)&k2b, g_k2);
    cudaGetSymbolAddress((void**)&ab,  g_attn);

    dim3 pg(BDIM/128, MROWS/128);   // (8, 72)
    proj_mma3<1><<<pg, 256>>>(query, Wq, bq, qb);
    proj_mma3<1><<<pg, 256>>>(key,   Wk, bk, kb);
    proj_mma3<1><<<pg, 256>>>(value, Wv, bv, vb);

    const int rtot = NB*NH*NSEQ*32;
    rope2_kernel<<<(rtot + 255)/256, 256>>>(qb, q2b);
    rope2_kernel<<<(rtot + 255)/256, 256>>>(kb, k2b);

    flash_kernel<<<dim3(NSEQ/128, NB*NH), 256>>>();

    proj_mma3<0><<<pg, 256>>>(ab, Wo, bo, (float*)d_out);
}